// round 15
// baseline (speedup 1.0000x reference)
#include <cuda_runtime.h>
#include <cuda_bf16.h>
#include <cuda_fp16.h>
#include <math.h>
#include <stdint.h>

// Problem constants
#define NSEQ 2048
#define DIM  2048
#define HEADS 32
#define KVHEADS 4
#define HD 64
#define KVDIM (KVHEADS*HD)   // 256
#define REP (HEADS/KVHEADS)  // 8
#define KP (DIM/2)           // k-pairs per row (all GEMMs have K=DIM)

// ---------------- scratch ----------------
__device__ uint32_t g_xh[NSEQ * KP];          // x, fp16 hi packed
__device__ uint32_t g_wqh[DIM * KP], g_wql[DIM * KP];
__device__ uint32_t g_wkh[KVDIM * KP], g_wkl[KVDIM * KP];
__device__ uint32_t g_wvh[KVDIM * KP], g_wvl[KVDIM * KP];
__device__ uint32_t g_woh[DIM * KP], g_wol[DIM * KP];
__device__ uint32_t g_qh[NSEQ * DIM / 2];     // roped+scaled Q, hi/lo
__device__ uint32_t g_ql[NSEQ * DIM / 2];
__device__ uint32_t g_kh[NSEQ * KVDIM / 2];   // roped K, hi
__device__ float    g_v[NSEQ * KVDIM];        // V fp32
__device__ uint32_t g_yh[NSEQ * KP];          // attention out, fp16 hi packed

// ---------------- helpers ----------------
__device__ __forceinline__ float ex2(float x) {
    float r;
    asm("ex2.approx.f32 %0, %1;" : "=f"(r) : "f"(x));
    return r;
}

__device__ __forceinline__ uint32_t pkhf(float x0, float x1) {
    __half2 h = __floats2half2_rn(x0, x1);
    return *reinterpret_cast<uint32_t*>(&h);
}

__device__ __forceinline__ void split2h(float x0, float x1, uint32_t& hi, uint32_t& lo) {
    float h0 = __half2float(__float2half_rn(x0));
    float h1 = __half2float(__float2half_rn(x1));
    hi = pkhf(h0, h1);
    lo = pkhf(x0 - h0, x1 - h1);
}

__device__ __forceinline__ void mma_f16(float* d, const uint32_t* a, const uint32_t* b) {
    asm volatile(
        "mma.sync.aligned.m16n8k16.row.col.f32.f16.f16.f32 "
        "{%0,%1,%2,%3}, {%4,%5,%6,%7}, {%8,%9}, {%0,%1,%2,%3};"
        : "+f"(d[0]), "+f"(d[1]), "+f"(d[2]), "+f"(d[3])
        : "r"(a[0]), "r"(a[1]), "r"(a[2]), "r"(a[3]), "r"(b[0]), "r"(b[1]));
}

#define SCL2E 0.18033688f   // 0.125 * log2(e)

// ---------------- one-shot conversion: x -> hi; weights -> hi+lo ----------------
__global__ void __launch_bounds__(256)
conv_all(const float* __restrict__ x,  const float* __restrict__ Wq,
         const float* __restrict__ Wk, const float* __restrict__ Wv,
         const float* __restrict__ Wo,
         uint32_t* __restrict__ xh,
         uint32_t* __restrict__ wqh, uint32_t* __restrict__ wql,
         uint32_t* __restrict__ wkh, uint32_t* __restrict__ wkl,
         uint32_t* __restrict__ wvh, uint32_t* __restrict__ wvl,
         uint32_t* __restrict__ woh, uint32_t* __restrict__ wol)
{
    int i = blockIdx.x * 256 + threadIdx.x;
    uint32_t hi, lo;
    switch (blockIdx.y) {
    case 0:
        if (i < NSEQ * KP) {
            float2 v = ((const float2*)x)[i];
            xh[i] = pkhf(v.x, v.y);
        }
        break;
    case 1:
        if (i < DIM * KP) {
            float2 v = ((const float2*)Wq)[i];
            split2h(v.x, v.y, hi, lo);
            wqh[i] = hi; wql[i] = lo;
        }
        break;
    case 2:
        if (i < KVDIM * KP) {
            float2 v = ((const float2*)Wk)[i];
            split2h(v.x, v.y, hi, lo);
            wkh[i] = hi; wkl[i] = lo;
        }
        break;
    case 3:
        if (i < KVDIM * KP) {
            float2 v = ((const float2*)Wv)[i];
            split2h(v.x, v.y, hi, lo);
            wvh[i] = hi; wvl[i] = lo;
        }
        break;
    default:
        if (i < DIM * KP) {
            float2 v = ((const float2*)Wo)[i];
            split2h(v.x, v.y, hi, lo);
            woh[i] = hi; wol[i] = lo;
        }
        break;
    }
}

// ---------------- fp16 NT GEMM core (register-prefetch, double-buffered) ------
// C = A(hi) * (B(hi)+B(lo))^T. CTA tile 128x64, BK=16 pairs, 256 threads,
// 8 warps of 32x32. All operands pre-packed fp16. One __syncthreads per tile:
//   LDG(s+1) -> MMA(s) -> STS(s+1 -> other buf) -> sync
#define GLDSW 20
#define GSA (128 * GLDSW)
#define GSB (64 * GLDSW)
#define GSTAGE (GSA + 2 * GSB)       // 5120 u32 per stage

__device__ __forceinline__ void gemm_ldg(const uint32_t* __restrict__ Ag,
                                         const uint32_t* __restrict__ Bhg,
                                         const uint32_t* __restrict__ Blg,
                                         int m0, int n0, int kp0, int tid,
                                         uint4* pa, uint4* pb)
{
    #pragma unroll
    for (int i = 0; i < 2; i++) {
        int idx = tid + i * 256;              // 0..511, A: 128 rows x 4 chunks
        int row = idx >> 2, c = (idx & 3) * 4;
        pa[i] = *(const uint4*)&Ag[(size_t)(m0 + row) * KP + kp0 + c];
    }
    #pragma unroll
    for (int i = 0; i < 2; i++) {
        int idx = tid + i * 256;              // B: 2 planes x 64 rows x 4 chunks
        int pl = idx >> 8, row = (idx >> 2) & 63, c = (idx & 3) * 4;
        const uint32_t* src = (pl ? Blg : Bhg) + (size_t)(n0 + row) * KP + kp0 + c;
        pb[i] = *(const uint4*)src;
    }
}

__device__ __forceinline__ void gemm_sts(uint32_t* st, const uint4* pa,
                                         const uint4* pb, int tid)
{
    #pragma unroll
    for (int i = 0; i < 2; i++) {
        int idx = tid + i * 256;
        int row = idx >> 2, c = (idx & 3) * 4;
        *(uint4*)&st[row * GLDSW + c] = pa[i];
    }
    #pragma unroll
    for (int i = 0; i < 2; i++) {
        int idx = tid + i * 256;
        int pl = idx >> 8, row = (idx >> 2) & 63, c = (idx & 3) * 4;
        *(uint4*)&st[GSA + pl * GSB + row * GLDSW + c] = pb[i];
    }
}

// MODE: 0 = plain fp32 store to C; 1 = rope+scale Q pack hi/lo; 2 = rope K pack hi
template<int MODE>
__device__ __forceinline__ void gemm_core(const uint32_t* __restrict__ Ag,
                                          const uint32_t* __restrict__ Bhg,
                                          const uint32_t* __restrict__ Blg,
                                          float* __restrict__ C,
                                          int m0, int n0, int N,
                                          uint32_t* sm,
                                          const float* __restrict__ cosd,
                                          const float* __restrict__ sind,
                                          uint32_t* __restrict__ outh,
                                          uint32_t* __restrict__ outl,
                                          int head)
{
    const int tid  = threadIdx.x;
    const int lane = tid & 31;
    const int warp = tid >> 5;
    const int wm   = warp >> 1;
    const int wn   = warp & 1;
    const int qz   = lane & 3;
    const int lr   = lane >> 2;

    float acc[2][4][4];
    #pragma unroll
    for (int i = 0; i < 2; i++)
        #pragma unroll
        for (int j = 0; j < 4; j++)
            #pragma unroll
            for (int r = 0; r < 4; r++) acc[i][j][r] = 0.f;

    uint4 pa[2], pb[2];
    gemm_ldg(Ag, Bhg, Blg, m0, n0, 0, tid, pa, pb);
    gemm_sts(sm, pa, pb, tid);
    __syncthreads();

    const int S = KP / 16;   // 64 k-tiles of 16 pairs
    for (int s = 0; s < S; s++) {
        uint32_t* st = sm + (s & 1) * GSTAGE;
        uint32_t* Ah = st;
        uint32_t* Bh = st + GSA;
        uint32_t* Bl = st + GSA + GSB;

        if (s + 1 < S)
            gemm_ldg(Ag, Bhg, Blg, m0, n0, (s + 1) * 16, tid, pa, pb);

        #pragma unroll
        for (int ks = 0; ks < 2; ks++) {
            const int c0 = ks * 8 + qz;
            uint32_t ah[2][4], bh[4][2], bl[4][2];
            #pragma unroll
            for (int i = 0; i < 2; i++) {
                int r0 = wm * 32 + i * 16 + lr;
                ah[i][0] = Ah[r0 * GLDSW + c0];
                ah[i][1] = Ah[(r0 + 8) * GLDSW + c0];
                ah[i][2] = Ah[r0 * GLDSW + c0 + 4];
                ah[i][3] = Ah[(r0 + 8) * GLDSW + c0 + 4];
            }
            #pragma unroll
            for (int j = 0; j < 4; j++) {
                int nr = wn * 32 + j * 8 + lr;
                bh[j][0] = Bh[nr * GLDSW + c0];
                bh[j][1] = Bh[nr * GLDSW + c0 + 4];
                bl[j][0] = Bl[nr * GLDSW + c0];
                bl[j][1] = Bl[nr * GLDSW + c0 + 4];
            }
            #pragma unroll
            for (int i = 0; i < 2; i++)
                #pragma unroll
                for (int j = 0; j < 4; j++) {
                    mma_f16(acc[i][j], ah[i], bh[j]);
                    mma_f16(acc[i][j], ah[i], bl[j]);
                }
        }

        if (s + 1 < S)
            gemm_sts(sm + ((s + 1) & 1) * GSTAGE, pa, pb, tid);
        __syncthreads();
    }

    if (MODE == 0) {
        #pragma unroll
        for (int i = 0; i < 2; i++) {
            #pragma unroll
            for (int j = 0; j < 4; j++) {
                int row = m0 + wm * 32 + i * 16 + lr;
                int col = n0 + wn * 32 + j * 8 + qz * 2;
                *(float2*)&C[(size_t)row * N + col]       = make_float2(acc[i][j][0], acc[i][j][1]);
                *(float2*)&C[(size_t)(row + 8) * N + col] = make_float2(acc[i][j][2], acc[i][j][3]);
            }
        }
    } else {
        // rope epilogue: round-trip 128x64 tile through (free) stage smem
        const int EPL = 66;
        float* sf = (float*)sm;
        #pragma unroll
        for (int i = 0; i < 2; i++) {
            #pragma unroll
            for (int j = 0; j < 4; j++) {
                int row = wm * 32 + i * 16 + lr;
                int col = wn * 32 + j * 8 + qz * 2;
                *(float2*)&sf[row * EPL + col]       = make_float2(acc[i][j][0], acc[i][j][1]);
                *(float2*)&sf[(row + 8) * EPL + col] = make_float2(acc[i][j][2], acc[i][j][3]);
            }
        }
        __syncthreads();
        for (int i = tid; i < 128 * 32; i += 256) {
            int row = i >> 5, p = i & 31;
            int n = m0 + row;
            int d0 = 2 * p, d1 = 2 * p + 1;
            float c0 = cosd[n * HD + d0], s0v = sind[n * HD + d0];
            float c1 = cosd[n * HD + d1], s1v = sind[n * HD + d1];
            float x0 = sf[row * EPL + d0];
            float x1 = sf[row * EPL + d1];
            float o0, o1;
            if (p < 16) {
                o0 = x0 * c0 - sf[row * EPL + d0 + 32] * s0v;
                o1 = x1 * c1 - sf[row * EPL + d1 + 32] * s1v;
            } else {
                o0 = x0 * c0 + sf[row * EPL + d0 - 32] * s0v;
                o1 = x1 * c1 + sf[row * EPL + d1 - 32] * s1v;
            }
            if (MODE == 1) {
                o0 *= SCL2E; o1 *= SCL2E;
                uint32_t hi, lo;
                split2h(o0, o1, hi, lo);
                size_t g = (size_t)n * (DIM / 2) + head * 32 + p;
                outh[g] = hi;
                outl[g] = lo;
            } else {
                outh[(size_t)n * (KVDIM / 2) + head * 32 + p] = pkhf(o0, o1);
            }
        }
    }
}

// ---- fused Q+K+V projection: bx 0..31 Q (head bx), 32..35 K, 36..39 V
__global__ void __launch_bounds__(256, 3)
proj_qkv(const uint32_t* __restrict__ xh,
         const uint32_t* __restrict__ wqh, const uint32_t* __restrict__ wql,
         const uint32_t* __restrict__ wkh, const uint32_t* __restrict__ wkl,
         const uint32_t* __restrict__ wvh, const uint32_t* __restrict__ wvl,
         float* __restrict__ vp,
         const float* __restrict__ cosd, const float* __restrict__ sind,
         uint32_t* __restrict__ qh, uint32_t* __restrict__ ql,
         uint32_t* __restrict__ kh)
{
    extern __shared__ uint32_t sm[];
    const int bx = blockIdx.x;
    const int m0 = blockIdx.y * 128;
    if (bx < 32) {
        gemm_core<1>(xh, wqh, wql, nullptr, m0, bx * 64, DIM, sm,
                     cosd, sind, qh, ql, bx);
    } else if (bx < 36) {
        gemm_core<2>(xh, wkh, wkl, nullptr, m0, (bx - 32) * 64, KVDIM, sm,
                     cosd, sind, kh, nullptr, bx - 32);
    } else {
        gemm_core<0>(xh, wvh, wvl, vp, m0, (bx - 36) * 64, KVDIM, sm,
                     nullptr, nullptr, nullptr, nullptr, 0);
    }
}

__global__ void __launch_bounds__(256, 3)
proj_o(const uint32_t* __restrict__ yh,
       const uint32_t* __restrict__ woh, const uint32_t* __restrict__ wol,
       float* __restrict__ out)
{
    extern __shared__ uint32_t sm[];
    gemm_core<0>(yh, woh, wol, out, blockIdx.y * 128, blockIdx.x * 64, DIM, sm,
                 nullptr, nullptr, nullptr, nullptr, 0);
}

// ---------------- MMA flash attention (causal; rope pre-applied) --------------
// Scores: 2xfp16 — Q(hi+lo) x K(hi). PV: 2xfp16 — P(hi) x V(hi+lo).
#define LDQ 36
#define LDV 36

__global__ void __launch_bounds__(256, 2)
attn_mma(const uint32_t* __restrict__ Qh, const uint32_t* __restrict__ Ql,
         const uint32_t* __restrict__ Kh, const float* __restrict__ Vg,
         uint32_t* __restrict__ Yh)
{
    extern __shared__ uint32_t sm[];
    uint32_t* Qhi = sm;                  // [128][LDQ]
    uint32_t* Qlo = Qhi + 128 * LDQ;
    uint32_t* Ksh = Qlo + 128 * LDQ;     // [64][LDQ]
    uint32_t* Vhi = Ksh + 64 * LDQ;      // [64 d][LDV kp]
    uint32_t* Vlo = Vhi + 64 * LDV;

    const int tid  = threadIdx.x;
    const int lane = tid & 31;
    const int warp = tid >> 5;
    const int qb   = (gridDim.x - 1) - blockIdx.x;
    const int h    = blockIdx.y;
    const int kvh  = h >> 3;
    const int wrow = warp * 16;
    const int r0   = wrow + (lane >> 2);
    const int qz   = lane & 3;

    for (int i = tid; i < 128 * 32; i += 256) {
        int row = i >> 5, p = i & 31;
        size_t g = (size_t)(qb * 128 + row) * (DIM / 2) + h * 32 + p;
        Qhi[row * LDQ + p] = Qh[g];
        Qlo[row * LDQ + p] = Ql[g];
    }

    float yacc[8][4];
    #pragma unroll
    for (int nf = 0; nf < 8; nf++)
        #pragma unroll
        for (int r = 0; r < 4; r++) yacc[nf][r] = 0.f;
    float m0 = -1e30f, m1 = -1e30f, l0 = 0.f, l1 = 0.f;

    const int arow0 = qb * 128 + r0;
    const int arow1 = arow0 + 8;
    const int ntiles = 2 * qb + 2;

    for (int t = 0; t < ntiles; t++) {
        const int s0k = t * 64;
        for (int i = tid; i < 64 * 32; i += 256) {
            int row = i >> 5, p = i & 31;
            Ksh[row * LDQ + p] = Kh[(size_t)(s0k + row) * (KVDIM / 2) + kvh * 32 + p];
        }
        for (int i = tid; i < 64 * 32; i += 256) {
            int d = i & 63, kp = i >> 6;
            float v0 = Vg[(size_t)(s0k + 2*kp)     * KVDIM + kvh * HD + d];
            float v1 = Vg[(size_t)(s0k + 2*kp + 1) * KVDIM + kvh * HD + d];
            uint32_t hi, lo;
            split2h(v0, v1, hi, lo);
            Vhi[d * LDV + kp] = hi;
            Vlo[d * LDV + kp] = lo;
        }
        __syncthreads();

        float s[8][4];
        #pragma unroll
        for (int nf = 0; nf < 8; nf++)
            #pragma unroll
            for (int r = 0; r < 4; r++) s[nf][r] = 0.f;

        #pragma unroll
        for (int ko = 0; ko < 4; ko++) {
            const int c = ko * 8 + qz;
            uint32_t ah[4], al[4];
            ah[0] = Qhi[r0 * LDQ + c];
            ah[1] = Qhi[(r0 + 8) * LDQ + c];
            ah[2] = Qhi[r0 * LDQ + c + 4];
            ah[3] = Qhi[(r0 + 8) * LDQ + c + 4];
            al[0] = Qlo[r0 * LDQ + c];
            al[1] = Qlo[(r0 + 8) * LDQ + c];
            al[2] = Qlo[r0 * LDQ + c + 4];
            al[3] = Qlo[(r0 + 8) * LDQ + c + 4];
            #pragma unroll
            for (int nf = 0; nf < 8; nf++) {
                const int kn = nf * 8 + (lane >> 2);
                uint32_t b[2];
                b[0] = Ksh[kn * LDQ + c];
                b[1] = Ksh[kn * LDQ + c + 4];
                mma_f16(s[nf], ah, b);
                mma_f16(s[nf], al, b);
            }
        }

        if (s0k + 63 > qb * 128 + wrow) {
            #pragma unroll
            for (int nf = 0; nf < 8; nf++) {
                int key = s0k + nf * 8 + 2 * qz;
                if (key     > arow0) s[nf][0] = -1e30f;
                if (key + 1 > arow0) s[nf][1] = -1e30f;
                if (key     > arow1) s[nf][2] = -1e30f;
                if (key + 1 > arow1) s[nf][3] = -1e30f;
            }
        }

        float t0 = -1e30f, t1 = -1e30f;
        #pragma unroll
        for (int nf = 0; nf < 8; nf++) {
            t0 = fmaxf(t0, fmaxf(s[nf][0], s[nf][1]));
            t1 = fmaxf(t1, fmaxf(s[nf][2], s[nf][3]));
        }
        t0 = fmaxf(t0, __shfl_xor_sync(0xffffffff, t0, 1));
        t0 = fmaxf(t0, __shfl_xor_sync(0xffffffff, t0, 2));
        t1 = fmaxf(t1, __shfl_xor_sync(0xffffffff, t1, 1));
        t1 = fmaxf(t1, __shfl_xor_sync(0xffffffff, t1, 2));
        float nm0 = fmaxf(m0, t0), nm1 = fmaxf(m1, t1);
        float cor0 = ex2(m0 - nm0), cor1 = ex2(m1 - nm1);
        m0 = nm0; m1 = nm1;

        float ls0 = 0.f, ls1 = 0.f;
        #pragma unroll
        for (int nf = 0; nf < 8; nf++) {
            s[nf][0] = ex2(s[nf][0] - m0);
            s[nf][1] = ex2(s[nf][1] - m0);
            s[nf][2] = ex2(s[nf][2] - m1);
            s[nf][3] = ex2(s[nf][3] - m1);
            ls0 += s[nf][0] + s[nf][1];
            ls1 += s[nf][2] + s[nf][3];
        }
        ls0 += __shfl_xor_sync(0xffffffff, ls0, 1);
        ls0 += __shfl_xor_sync(0xffffffff, ls0, 2);
        ls1 += __shfl_xor_sync(0xffffffff, ls1, 1);
        ls1 += __shfl_xor_sync(0xffffffff, ls1, 2);
        l0 = l0 * cor0 + ls0;
        l1 = l1 * cor1 + ls1;
        #pragma unroll
        for (int nf = 0; nf < 8; nf++) {
            yacc[nf][0] *= cor0; yacc[nf][1] *= cor0;
            yacc[nf][2] *= cor1; yacc[nf][3] *= cor1;
        }

        #pragma unroll
        for (int ko = 0; ko < 4; ko++) {
            uint32_t ah[4];
            ah[0] = pkhf(s[2*ko][0],     s[2*ko][1]);
            ah[1] = pkhf(s[2*ko][2],     s[2*ko][3]);
            ah[2] = pkhf(s[2*ko + 1][0], s[2*ko + 1][1]);
            ah[3] = pkhf(s[2*ko + 1][2], s[2*ko + 1][3]);
            #pragma unroll
            for (int nf = 0; nf < 8; nf++) {
                const int d = nf * 8 + (lane >> 2);
                uint32_t bh[2], bl[2];
                bh[0] = Vhi[d * LDV + ko * 8 + qz];
                bh[1] = Vhi[d * LDV + ko * 8 + qz + 4];
                bl[0] = Vlo[d * LDV + ko * 8 + qz];
                bl[1] = Vlo[d * LDV + ko * 8 + qz + 4];
                mma_f16(yacc[nf], ah, bh);
                mma_f16(yacc[nf], ah, bl);
            }
        }
        __syncthreads();
    }

    // epilogue: write y as packed fp16 hi pairs
    float i0 = 1.f / l0, i1 = 1.f / l1;
    #pragma unroll
    for (int nf = 0; nf < 8; nf++) {
        int colp = h * 32 + nf * 4 + qz;   // pair index of (h*64 + nf*8 + 2qz)
        Yh[(size_t)arow0 * KP + colp] = pkhf(yacc[nf][0] * i0, yacc[nf][1] * i0);
        Yh[(size_t)arow1 * KP + colp] = pkhf(yacc[nf][2] * i1, yacc[nf][3] * i1);
    }
}

// ---------------- launch ----------------
extern "C" void kernel_launch(void* const* d_in, const int* in_sizes, int n_in,
                              void* d_out, int out_size)
{
    const float* x   = (const float*)d_in[0];
    const float* Wq  = (const float*)d_in[1];
    const float* Wk  = (const float*)d_in[2];
    const float* Wv  = (const float*)d_in[3];
    const float* Wo  = (const float*)d_in[4];
    const float* cosd= (const float*)d_in[5];
    const float* sind= (const float*)d_in[6];
    float* out = (float*)d_out;

    uint32_t *xh, *wqh, *wql, *wkh, *wkl, *wvh, *wvl, *woh, *wol;
    uint32_t *qh, *ql, *kh, *yh;
    float *vp;
    cudaGetSymbolAddress((void**)&xh,  g_xh);
    cudaGetSymbolAddress((void**)&wqh, g_wqh);
    cudaGetSymbolAddress((void**)&wql, g_wql);
    cudaGetSymbolAddress((void**)&wkh, g_wkh);
    cudaGetSymbolAddress((void**)&wkl, g_wkl);
    cudaGetSymbolAddress((void**)&wvh, g_wvh);
    cudaGetSymbolAddress((void**)&wvl, g_wvl);
    cudaGetSymbolAddress((void**)&woh, g_woh);
    cudaGetSymbolAddress((void**)&wol, g_wol);
    cudaGetSymbolAddress((void**)&qh,  g_qh);
    cudaGetSymbolAddress((void**)&ql,  g_ql);
    cudaGetSymbolAddress((void**)&kh,  g_kh);
    cudaGetSymbolAddress((void**)&vp,  g_v);
    cudaGetSymbolAddress((void**)&yh,  g_yh);

    constexpr int SMEM_G = 2 * GSTAGE * 4;                         // 40960 B
    constexpr int SMEM_ATTN = (2*128*LDQ + 64*LDQ + 2*64*LDV) * 4; // 64512 B
    cudaFuncSetAttribute(proj_qkv,
                         cudaFuncAttributeMaxDynamicSharedMemorySize, SMEM_G);
    cudaFuncSetAttribute(proj_o,
                         cudaFuncAttributeMaxDynamicSharedMemorySize, SMEM_G);
    cudaFuncSetAttribute(attn_mma,
                         cudaFuncAttributeMaxDynamicSharedMemorySize, SMEM_ATTN);

    // 0: one-shot conversions (x -> hi; weights -> hi+lo)
    conv_all<<<dim3((DIM * KP + 255) / 256, 5), 256>>>(
        x, Wq, Wk, Wv, Wo, xh, wqh, wql, wkh, wkl, wvh, wvl, woh, wol);
    // 1: fused Q+K+V projections with rope/pack epilogues
    proj_qkv<<<dim3(40, 16), 256, SMEM_G>>>(xh, wqh, wql, wkh, wkl, wvh, wvl,
                                            vp, cosd, sind, qh, ql, kh);
    // 2: flash attention (rope pre-applied) -> packed fp16 y
    attn_mma<<<dim3(16, HEADS), 256, SMEM_ATTN>>>(qh, ql, kh, vp, yh);
    // 3: output projection
    proj_o<<<dim3(32, 16), 256, SMEM_G>>>(yh, woh, wol, out);
}

// round 16
// speedup vs baseline: 1.1800x; 1.1800x over previous
#include <cuda_runtime.h>
#include <cuda_bf16.h>
#include <cuda_fp16.h>
#include <math.h>
#include <stdint.h>

// Problem constants
#define NSEQ 2048
#define DIM  2048
#define HEADS 32
#define KVHEADS 4
#define HD 64
#define KVDIM (KVHEADS*HD)   // 256
#define REP (HEADS/KVHEADS)  // 8

// ---------------- scratch ----------------
__device__ uint32_t g_qh[NSEQ * DIM / 2];     // roped+scaled Q, fp16 hi packed
__device__ uint32_t g_kh[NSEQ * KVDIM / 2];   // roped K, fp16 hi packed
__device__ uint32_t g_vh[KVDIM * NSEQ / 2];   // V transposed [kvh*64+d][keypair], hi
__device__ uint32_t g_vl[KVDIM * NSEQ / 2];   // lo plane
__device__ float    g_y[NSEQ * DIM];          // attention out, fp32

// ---------------- helpers ----------------
__device__ __forceinline__ float ex2(float x) {
    float r;
    asm("ex2.approx.f32 %0, %1;" : "=f"(r) : "f"(x));
    return r;
}

__device__ __forceinline__ uint32_t pkhf(float x0, float x1) {
    __half2 h = __floats2half2_rn(x0, x1);
    return *reinterpret_cast<uint32_t*>(&h);
}

__device__ __forceinline__ void split2h(float x0, float x1, uint32_t& hi, uint32_t& lo) {
    float h0 = __half2float(__float2half_rn(x0));
    float h1 = __half2float(__float2half_rn(x1));
    hi = pkhf(h0, h1);
    lo = pkhf(x0 - h0, x1 - h1);
}

__device__ __forceinline__ void mma_f16(float* d, const uint32_t* a, const uint32_t* b) {
    asm volatile(
        "mma.sync.aligned.m16n8k16.row.col.f32.f16.f16.f32 "
        "{%0,%1,%2,%3}, {%4,%5,%6,%7}, {%8,%9}, {%0,%1,%2,%3};"
        : "+f"(d[0]), "+f"(d[1]), "+f"(d[2]), "+f"(d[3])
        : "r"(a[0]), "r"(a[1]), "r"(a[2]), "r"(a[3]), "r"(b[0]), "r"(b[1]));
}

#define SCL2E 0.18033688f   // 0.125 * log2(e)

// ---------------- 2xFP16 NT GEMM core (R13: 128x64, double-buffered) ----------
// C = A(hi) * (B(hi)+B(lo))^T. 256 threads, 8 warps of 32x32.
// One __syncthreads per k-tile: LDG(s+1) -> MMA(s) -> STS(s+1) -> sync.
#define GLDSW 20
#define GSA (128 * GLDSW)
#define GSB (64 * GLDSW)
#define GSTAGE (GSA + 2 * GSB)       // 5120 u32 per stage

__device__ __forceinline__ void gemm_ldg(const float* __restrict__ A,
                                         const float* __restrict__ B,
                                         int m0, int n0, int K, int k0, int tid,
                                         float4* pa, float4* pb)
{
    #pragma unroll
    for (int i = 0; i < 4; i++) {
        int idx = tid + i * 256;
        int row = idx >> 3, kq = (idx & 7) * 4;
        pa[i] = *(const float4*)&A[(size_t)(m0 + row) * K + k0 + kq];
    }
    #pragma unroll
    for (int i = 0; i < 2; i++) {
        int idx = tid + i * 256;
        int row = idx >> 3, kq = (idx & 7) * 4;
        pb[i] = *(const float4*)&B[(size_t)(n0 + row) * K + k0 + kq];
    }
}

__device__ __forceinline__ void gemm_sts(uint32_t* st, const float4* pa,
                                         const float4* pb, int tid)
{
    uint32_t* Ah = st;
    uint32_t* Bh = st + GSA;
    uint32_t* Bl = st + GSA + GSB;
    #pragma unroll
    for (int i = 0; i < 4; i++) {
        int idx = tid + i * 256;
        int row = idx >> 3, kq = (idx & 7) * 4;
        Ah[row * GLDSW + kq/2]     = pkhf(pa[i].x, pa[i].y);
        Ah[row * GLDSW + kq/2 + 1] = pkhf(pa[i].z, pa[i].w);
    }
    #pragma unroll
    for (int i = 0; i < 2; i++) {
        int idx = tid + i * 256;
        int row = idx >> 3, kq = (idx & 7) * 4;
        uint32_t h01, l01, h23, l23;
        split2h(pb[i].x, pb[i].y, h01, l01);
        split2h(pb[i].z, pb[i].w, h23, l23);
        Bh[row * GLDSW + kq/2]     = h01;
        Bh[row * GLDSW + kq/2 + 1] = h23;
        Bl[row * GLDSW + kq/2]     = l01;
        Bl[row * GLDSW + kq/2 + 1] = l23;
    }
}

// MODE: 0 = plain fp32 store to C
//       1 = rope + scale, pack fp16 hi -> outh at [n*(DIM/2) + head*32 + p]
//       2 = rope, pack fp16 hi -> outh at [n*(KVDIM/2) + head*32 + p]
//       3 = V transpose+split -> outh/outl at [(head*64+d)*(NSEQ/2) + keypair]
template<int MODE>
__device__ __forceinline__ void gemm_core(const float* __restrict__ A,
                                          const float* __restrict__ B,
                                          float* __restrict__ C,
                                          int m0, int n0, int N, int K,
                                          uint32_t* sm,
                                          const float* __restrict__ cosd,
                                          const float* __restrict__ sind,
                                          uint32_t* __restrict__ outh,
                                          uint32_t* __restrict__ outl,
                                          int head)
{
    constexpr int BK = 32;
    const int tid  = threadIdx.x;
    const int lane = tid & 31;
    const int warp = tid >> 5;
    const int wm   = warp >> 1;
    const int wn   = warp & 1;
    const int qz   = lane & 3;
    const int lr   = lane >> 2;

    float acc[2][4][4];
    #pragma unroll
    for (int i = 0; i < 2; i++)
        #pragma unroll
        for (int j = 0; j < 4; j++)
            #pragma unroll
            for (int r = 0; r < 4; r++) acc[i][j][r] = 0.f;

    float4 pa[4], pb[2];
    gemm_ldg(A, B, m0, n0, K, 0, tid, pa, pb);
    gemm_sts(sm, pa, pb, tid);
    __syncthreads();

    const int S = K / BK;
    for (int s = 0; s < S; s++) {
        uint32_t* st = sm + (s & 1) * GSTAGE;
        uint32_t* Ah = st;
        uint32_t* Bh = st + GSA;
        uint32_t* Bl = st + GSA + GSB;

        if (s + 1 < S)
            gemm_ldg(A, B, m0, n0, K, (s + 1) * BK, tid, pa, pb);

        #pragma unroll
        for (int ks = 0; ks < 2; ks++) {
            const int c0 = ks * 8 + qz;
            uint32_t ah[2][4], bh[4][2], bl[4][2];
            #pragma unroll
            for (int i = 0; i < 2; i++) {
                int r0 = wm * 32 + i * 16 + lr;
                ah[i][0] = Ah[r0 * GLDSW + c0];
                ah[i][1] = Ah[(r0 + 8) * GLDSW + c0];
                ah[i][2] = Ah[r0 * GLDSW + c0 + 4];
                ah[i][3] = Ah[(r0 + 8) * GLDSW + c0 + 4];
            }
            #pragma unroll
            for (int j = 0; j < 4; j++) {
                int nr = wn * 32 + j * 8 + lr;
                bh[j][0] = Bh[nr * GLDSW + c0];
                bh[j][1] = Bh[nr * GLDSW + c0 + 4];
                bl[j][0] = Bl[nr * GLDSW + c0];
                bl[j][1] = Bl[nr * GLDSW + c0 + 4];
            }
            #pragma unroll
            for (int i = 0; i < 2; i++)
                #pragma unroll
                for (int j = 0; j < 4; j++) {
                    mma_f16(acc[i][j], ah[i], bh[j]);
                    mma_f16(acc[i][j], ah[i], bl[j]);
                }
        }

        if (s + 1 < S)
            gemm_sts(sm + ((s + 1) & 1) * GSTAGE, pa, pb, tid);
        __syncthreads();
    }

    if (MODE == 0) {
        #pragma unroll
        for (int i = 0; i < 2; i++) {
            #pragma unroll
            for (int j = 0; j < 4; j++) {
                int row = m0 + wm * 32 + i * 16 + lr;
                int col = n0 + wn * 32 + j * 8 + qz * 2;
                *(float2*)&C[(size_t)row * N + col]       = make_float2(acc[i][j][0], acc[i][j][1]);
                *(float2*)&C[(size_t)(row + 8) * N + col] = make_float2(acc[i][j][2], acc[i][j][3]);
            }
        }
    } else {
        // epilogue: round-trip the 128x64 fp32 tile through (free) stage smem
        const int EPL = 66;
        float* sf = (float*)sm;
        #pragma unroll
        for (int i = 0; i < 2; i++) {
            #pragma unroll
            for (int j = 0; j < 4; j++) {
                int row = wm * 32 + i * 16 + lr;
                int col = wn * 32 + j * 8 + qz * 2;
                *(float2*)&sf[row * EPL + col]       = make_float2(acc[i][j][0], acc[i][j][1]);
                *(float2*)&sf[(row + 8) * EPL + col] = make_float2(acc[i][j][2], acc[i][j][3]);
            }
        }
        __syncthreads();
        if (MODE == 3) {
            // transpose + split: rows = keys, cols = d. pair over keys.
            for (int i = tid; i < 64 * 64; i += 256) {
                int d = i >> 6, kp = i & 63;
                float v0 = sf[(2 * kp)     * EPL + d];
                float v1 = sf[(2 * kp + 1) * EPL + d];
                uint32_t hi, lo;
                split2h(v0, v1, hi, lo);
                size_t g = (size_t)(head * 64 + d) * (NSEQ / 2) + (m0 >> 1) + kp;
                outh[g] = hi;
                outl[g] = lo;
            }
        } else {
            for (int i = tid; i < 128 * 32; i += 256) {
                int row = i >> 5, p = i & 31;
                int n = m0 + row;
                int d0 = 2 * p, d1 = 2 * p + 1;
                float c0 = cosd[n * HD + d0], s0v = sind[n * HD + d0];
                float c1 = cosd[n * HD + d1], s1v = sind[n * HD + d1];
                float x0 = sf[row * EPL + d0];
                float x1 = sf[row * EPL + d1];
                float o0, o1;
                if (p < 16) {
                    o0 = x0 * c0 - sf[row * EPL + d0 + 32] * s0v;
                    o1 = x1 * c1 - sf[row * EPL + d1 + 32] * s1v;
                } else {
                    o0 = x0 * c0 + sf[row * EPL + d0 - 32] * s0v;
                    o1 = x1 * c1 + sf[row * EPL + d1 - 32] * s1v;
                }
                if (MODE == 1) {
                    o0 *= SCL2E; o1 *= SCL2E;
                    outh[(size_t)n * (DIM / 2) + head * 32 + p] = pkhf(o0, o1);
                } else {
                    outh[(size_t)n * (KVDIM / 2) + head * 32 + p] = pkhf(o0, o1);
                }
            }
        }
    }
}

// ---- fused Q+K+V projection: bx 0..31 Q (head bx), 32..35 K, 36..39 V
__global__ void __launch_bounds__(256, 2)
proj_qkv(const float* __restrict__ x,
         const float* __restrict__ Wq, const float* __restrict__ Wk,
         const float* __restrict__ Wv,
         const float* __restrict__ cosd, const float* __restrict__ sind,
         uint32_t* __restrict__ qh, uint32_t* __restrict__ kh,
         uint32_t* __restrict__ vh, uint32_t* __restrict__ vl)
{
    extern __shared__ uint32_t sm[];
    const int bx = blockIdx.x;
    const int m0 = blockIdx.y * 128;
    if (bx < 32) {
        gemm_core<1>(x, Wq, nullptr, m0, bx * 64, DIM, DIM, sm,
                     cosd, sind, qh, nullptr, bx);
    } else if (bx < 36) {
        gemm_core<2>(x, Wk, nullptr, m0, (bx - 32) * 64, KVDIM, DIM, sm,
                     cosd, sind, kh, nullptr, bx - 32);
    } else {
        gemm_core<3>(x, Wv, nullptr, m0, (bx - 36) * 64, KVDIM, DIM, sm,
                     nullptr, nullptr, vh, vl, bx - 36);
    }
}

__global__ void __launch_bounds__(256, 2)
proj_o(const float* __restrict__ yp, const float* __restrict__ Wo,
       float* __restrict__ out)
{
    extern __shared__ uint32_t sm[];
    gemm_core<0>(yp, Wo, out, blockIdx.y * 128, blockIdx.x * 64, DIM, DIM, sm,
                 nullptr, nullptr, nullptr, nullptr, 0);
}

// ---------------- MMA flash attention (causal; rope & packing pre-applied) ----
// Scores: fp16 — Q(hi) x K(hi). PV: 2xfp16 — P(hi) x V(hi+lo).
#define LDQ 36
#define LDV 36

__global__ void __launch_bounds__(256, 2)
attn_mma(const uint32_t* __restrict__ Qh, const uint32_t* __restrict__ Kh,
         const uint32_t* __restrict__ Vh, const uint32_t* __restrict__ Vl,
         float* __restrict__ Yg)
{
    extern __shared__ uint32_t sm[];
    uint32_t* Qhi = sm;                  // [128][LDQ]
    uint32_t* Ksh = Qhi + 128 * LDQ;     // [64][LDQ]
    uint32_t* Vhi = Ksh + 64 * LDQ;      // [64 d][LDV kp]
    uint32_t* Vlo = Vhi + 64 * LDV;

    const int tid  = threadIdx.x;
    const int lane = tid & 31;
    const int warp = tid >> 5;
    const int qb   = (gridDim.x - 1) - blockIdx.x;
    const int h    = blockIdx.y;
    const int kvh  = h >> 3;
    const int wrow = warp * 16;
    const int r0   = wrow + (lane >> 2);
    const int qz   = lane & 3;

    // ---- stage Q (plain copy) ----
    for (int i = tid; i < 128 * 32; i += 256) {
        int row = i >> 5, p = i & 31;
        Qhi[row * LDQ + p] = Qh[(size_t)(qb * 128 + row) * (DIM / 2) + h * 32 + p];
    }

    float yacc[8][4];
    #pragma unroll
    for (int nf = 0; nf < 8; nf++)
        #pragma unroll
        for (int r = 0; r < 4; r++) yacc[nf][r] = 0.f;
    float m0 = -1e30f, m1 = -1e30f, l0 = 0.f, l1 = 0.f;

    const int arow0 = qb * 128 + r0;
    const int arow1 = arow0 + 8;
    const int ntiles = 2 * qb + 2;

    for (int t = 0; t < ntiles; t++) {
        const int s0k = t * 64;
        // ---- stage K (plain copy) ----
        for (int i = tid; i < 64 * 32; i += 256) {
            int row = i >> 5, p = i & 31;
            Ksh[row * LDQ + p] = Kh[(size_t)(s0k + row) * (KVDIM / 2) + kvh * 32 + p];
        }
        // ---- stage V (plain copies of pre-transposed planes) ----
        for (int i = tid; i < 64 * 32; i += 256) {
            int d = i >> 5, kp = i & 31;
            size_t g = (size_t)(kvh * 64 + d) * (NSEQ / 2) + (s0k >> 1) + kp;
            Vhi[d * LDV + kp] = Vh[g];
            Vlo[d * LDV + kp] = Vl[g];
        }
        __syncthreads();

        // ---- scores: fp16 hi x hi ----
        float s[8][4];
        #pragma unroll
        for (int nf = 0; nf < 8; nf++)
            #pragma unroll
            for (int r = 0; r < 4; r++) s[nf][r] = 0.f;

        #pragma unroll
        for (int ko = 0; ko < 4; ko++) {
            const int c = ko * 8 + qz;
            uint32_t ah[4];
            ah[0] = Qhi[r0 * LDQ + c];
            ah[1] = Qhi[(r0 + 8) * LDQ + c];
            ah[2] = Qhi[r0 * LDQ + c + 4];
            ah[3] = Qhi[(r0 + 8) * LDQ + c + 4];
            #pragma unroll
            for (int nf = 0; nf < 8; nf++) {
                const int kn = nf * 8 + (lane >> 2);
                uint32_t b[2];
                b[0] = Ksh[kn * LDQ + c];
                b[1] = Ksh[kn * LDQ + c + 4];
                mma_f16(s[nf], ah, b);
            }
        }

        // ---- causal mask ----
        if (s0k + 63 > qb * 128 + wrow) {
            #pragma unroll
            for (int nf = 0; nf < 8; nf++) {
                int key = s0k + nf * 8 + 2 * qz;
                if (key     > arow0) s[nf][0] = -1e30f;
                if (key + 1 > arow0) s[nf][1] = -1e30f;
                if (key     > arow1) s[nf][2] = -1e30f;
                if (key + 1 > arow1) s[nf][3] = -1e30f;
            }
        }

        // ---- online softmax (base-2) ----
        float t0 = -1e30f, t1 = -1e30f;
        #pragma unroll
        for (int nf = 0; nf < 8; nf++) {
            t0 = fmaxf(t0, fmaxf(s[nf][0], s[nf][1]));
            t1 = fmaxf(t1, fmaxf(s[nf][2], s[nf][3]));
        }
        t0 = fmaxf(t0, __shfl_xor_sync(0xffffffff, t0, 1));
        t0 = fmaxf(t0, __shfl_xor_sync(0xffffffff, t0, 2));
        t1 = fmaxf(t1, __shfl_xor_sync(0xffffffff, t1, 1));
        t1 = fmaxf(t1, __shfl_xor_sync(0xffffffff, t1, 2));
        float nm0 = fmaxf(m0, t0), nm1 = fmaxf(m1, t1);
        float cor0 = ex2(m0 - nm0), cor1 = ex2(m1 - nm1);
        m0 = nm0; m1 = nm1;

        float ls0 = 0.f, ls1 = 0.f;
        #pragma unroll
        for (int nf = 0; nf < 8; nf++) {
            s[nf][0] = ex2(s[nf][0] - m0);
            s[nf][1] = ex2(s[nf][1] - m0);
            s[nf][2] = ex2(s[nf][2] - m1);
            s[nf][3] = ex2(s[nf][3] - m1);
            ls0 += s[nf][0] + s[nf][1];
            ls1 += s[nf][2] + s[nf][3];
        }
        ls0 += __shfl_xor_sync(0xffffffff, ls0, 1);
        ls0 += __shfl_xor_sync(0xffffffff, ls0, 2);
        ls1 += __shfl_xor_sync(0xffffffff, ls1, 1);
        ls1 += __shfl_xor_sync(0xffffffff, ls1, 2);
        l0 = l0 * cor0 + ls0;
        l1 = l1 * cor1 + ls1;
        #pragma unroll
        for (int nf = 0; nf < 8; nf++) {
            yacc[nf][0] *= cor0; yacc[nf][1] *= cor0;
            yacc[nf][2] *= cor1; yacc[nf][3] *= cor1;
        }

        // ---- PV: 2xfp16, P hi x V(hi+lo) ----
        #pragma unroll
        for (int ko = 0; ko < 4; ko++) {
            uint32_t ah[4];
            ah[0] = pkhf(s[2*ko][0],     s[2*ko][1]);
            ah[1] = pkhf(s[2*ko][2],     s[2*ko][3]);
            ah[2] = pkhf(s[2*ko + 1][0], s[2*ko + 1][1]);
            ah[3] = pkhf(s[2*ko + 1][2], s[2*ko + 1][3]);
            #pragma unroll
            for (int nf = 0; nf < 8; nf++) {
                const int d = nf * 8 + (lane >> 2);
                uint32_t bh[2], bl[2];
                bh[0] = Vhi[d * LDV + ko * 8 + qz];
                bh[1] = Vhi[d * LDV + ko * 8 + qz + 4];
                bl[0] = Vlo[d * LDV + ko * 8 + qz];
                bl[1] = Vlo[d * LDV + ko * 8 + qz + 4];
                mma_f16(yacc[nf], ah, bh);
                mma_f16(yacc[nf], ah, bl);
            }
        }
        __syncthreads();
    }

    float i0 = 1.f / l0, i1 = 1.f / l1;
    #pragma unroll
    for (int nf = 0; nf < 8; nf++) {
        int col = h * HD + nf * 8 + 2 * qz;
        *(float2*)&Yg[(size_t)arow0 * DIM + col] =
            make_float2(yacc[nf][0] * i0, yacc[nf][1] * i0);
        *(float2*)&Yg[(size_t)arow1 * DIM + col] =
            make_float2(yacc[nf][2] * i1, yacc[nf][3] * i1);
    }
}

// ---------------- launch ----------------
extern "C" void kernel_launch(void* const* d_in, const int* in_sizes, int n_in,
                              void* d_out, int out_size)
{
    const float* x   = (const float*)d_in[0];
    const float* Wq  = (const float*)d_in[1];
    const float* Wk  = (const float*)d_in[2];
    const float* Wv  = (const float*)d_in[3];
    const float* Wo  = (const float*)d_in[4];
    const float* cosd= (const float*)d_in[5];
    const float* sind= (const float*)d_in[6];
    float* out = (float*)d_out;

    uint32_t *qh, *kh, *vh, *vl;
    float *yp;
    cudaGetSymbolAddress((void**)&qh, g_qh);
    cudaGetSymbolAddress((void**)&kh, g_kh);
    cudaGetSymbolAddress((void**)&vh, g_vh);
    cudaGetSymbolAddress((void**)&vl, g_vl);
    cudaGetSymbolAddress((void**)&yp, g_y);

    constexpr int SMEM_G = 2 * GSTAGE * 4;                             // 40960 B
    constexpr int SMEM_ATTN = ((128 + 64) * LDQ + 2 * 64 * LDV) * 4;   // 46080 B
    cudaFuncSetAttribute(proj_qkv,
                         cudaFuncAttributeMaxDynamicSharedMemorySize, SMEM_G);
    cudaFuncSetAttribute(proj_o,
                         cudaFuncAttributeMaxDynamicSharedMemorySize, SMEM_G);
    cudaFuncSetAttribute(attn_mma,
                         cudaFuncAttributeMaxDynamicSharedMemorySize, SMEM_ATTN);

    // 1: fused Q+K+V projections with rope/pack/transpose epilogues
    proj_qkv<<<dim3(40, 16), 256, SMEM_G>>>(x, Wq, Wk, Wv, cosd, sind, qh, kh, vh, vl);
    // 2: flash attention (all operands pre-packed)
    attn_mma<<<dim3(16, HEADS), 256, SMEM_ATTN>>>(qh, kh, vh, vl, yp);
    // 3: output projection
    proj_o<<<dim3(32, 16), 256, SMEM_G>>>(yp, Wo, out);
}